// round 11
// baseline (speedup 1.0000x reference)
#include <cuda_runtime.h>
#include <cuda_bf16.h>

// Problem constants (fixed by setup_inputs): B=2, L=16, C=16, H=64, W=64
#define PB 2
#define PL 16
#define PC 16
#define PH 64
#define PW 64
#define PHW (PH * PW)          // 4096

#define FLOWS_ELEMS  (PB * PL * 2 * PHW)     // 262144
#define IMAGES_ELEMS (PB * PL * PC * PHW)    // 2097152

// Scratch (allocation-free: __device__ globals)
// cum2[b][l][pix] = (cum_x, cum_y) : B*L*HW float2 = 1 MB
__device__ float2 g_cum2[PB * PL * PHW];
// imgT[b][l][h][w][c] as float4 (c packed, 16B aligned): B*L*HW*4 float4 = 8 MB
__device__ float4 g_imgT[PB * PL * PHW * (PC / 4)];

#define CUM_BLOCKS   ((PB * PHW) / 256)              // 32
#define TRANS_BLOCKS ((PB * PL * PHW) / 256)         // 512

// ---------------------------------------------------------------------------
// Fused prep kernel (single launch):
//  blocks [0, CUM_BLOCKS)              : cumsum of flows over L per (b,h,w),
//                                        packed float2 (x,y) per (b,l,pix)
//  blocks [CUM_BLOCKS, +TRANS_BLOCKS)  : transpose images [B][L][C][H][W]
//                                        -> imgT [B][L][H][W][C]
// No intra-block divergence: each block does exactly one task.
// ---------------------------------------------------------------------------
__global__ void prep_kernel(const float* __restrict__ flows,
                            const float* __restrict__ images)
{
    if (blockIdx.x < CUM_BLOCKS) {
        int s = blockIdx.x * blockDim.x + threadIdx.x;   // 0 .. B*HW-1
        int b   = s / PHW;
        int pix = s - b * PHW;
        const float* src = flows + (size_t)b * (PL * 2 * PHW) + pix;
        float2* dst = g_cum2 + (size_t)b * (PL * PHW) + pix;
        float cx = 0.0f, cy = 0.0f;
#pragma unroll
        for (int l = 0; l < PL; ++l) {
            cx += src[(l * 2 + 0) * PHW];
            cy += src[(l * 2 + 1) * PHW];
            dst[l * PHW] = make_float2(cx, cy);
        }
    } else {
        int t = (blockIdx.x - CUM_BLOCKS) * blockDim.x + threadIdx.x; // 0 .. B*L*HW-1
        int bl  = t / PHW;
        int pix = t - bl * PHW;
        const float* src = images + (size_t)bl * (PC * PHW) + pix;
        float v[PC];
#pragma unroll
        for (int c = 0; c < PC; ++c) v[c] = src[c * PHW];
        float4* dst = g_imgT + (size_t)t * (PC / 4);
#pragma unroll
        for (int k = 0; k < PC / 4; ++k)
            dst[k] = make_float4(v[4 * k], v[4 * k + 1], v[4 * k + 2], v[4 * k + 3]);
    }
}

// ---------------------------------------------------------------------------
// Main pairwise bilinear gather-scan.
// block = 256 threads = 64 pixels x 4 channel-groups, grid = (HW/64, L, B).
// i = PL-1-blockIdx.y so the heaviest CTAs (long j-loops) launch FIRST and
// light CTAs back-fill the final wave (LPT scheduling -> shorter tail).
// The 4 lanes of a pixel-quad load 4 consecutive float4s -> one coalesced
// 64B request per corner per pixel; x-adjacent corners share a 128B line
// half the time. cum values for the whole block are staged in smem once,
// so the j-loop issues only the 4 corner LDGs.
// Arithmetic follows the reference's exact fp32 operation order:
//   rel = cum_i - cum_j;  g = wrap(base + rel);  r = (g+1)*0.5*W - 0.5
// so boundary/wrap discontinuities land on the same side as the reference.
// ---------------------------------------------------------------------------
__device__ __forceinline__ float wrapg(float g)
{
    // jnp.mod(g + 1, 2) - 1  (floor-mod; power-of-two divisor -> exact)
    float t = g + 1.0f;
    t = t - 2.0f * floorf(t * 0.5f);
    float r = t - 1.0f;
    return (r < -1.0f) ? r + 2.0f : r;   // matches the reference fixup
}

__global__ void __launch_bounds__(256, 4)
pscan_kernel(float* __restrict__ out)
{
    __shared__ float2 s_cum[PL * 64];                // up to 8 KB

    int tid = threadIdx.x;
    int cg  = tid & 3;                               // channel group: 4 floats
    int lp  = tid >> 2;                              // local pixel 0..63
    int pix = blockIdx.x * 64 + lp;                  // 0..4095
    int i   = (PL - 1) - blockIdx.y;                 // heavy CTAs first
    int b   = blockIdx.z;
    int h   = pix >> 6;
    int w   = pix & 63;

    // Stage cum[j][pix] for j = 0..i and all 64 block pixels into smem.
    const float2* cumBase = g_cum2 + (size_t)b * (PL * PHW) + blockIdx.x * 64;
    for (int idx = tid; idx < (i + 1) * 64; idx += 256) {
        int jj = idx >> 6;
        int pp = idx & 63;
        s_cum[idx] = cumBase[jj * PHW + pp];
    }
    __syncthreads();

    float bx = (w + 0.5f) * (2.0f / PW) - 1.0f;
    float by = (h + 0.5f) * (2.0f / PH) - 1.0f;

    float2 ci = s_cum[i * 64 + lp];
    float cix = ci.x;
    float ciy = ci.y;

    const float4* imgB = g_imgT + (size_t)(b * PL) * PHW * (PC / 4) + cg;

    float4 acc = make_float4(0.f, 0.f, 0.f, 0.f);

#pragma unroll 2
    for (int j = 0; j <= i; ++j) {
        float2 cj = s_cum[j * 64 + lp];

        // Reference order: rel first, then base + rel.
        float relx = cix - cj.x;
        float rely = ciy - cj.y;
        float gx = wrapg(bx + relx);
        float gy = wrapg(by + rely);
        float rx = (gx + 1.0f) * (0.5f * PW) - 0.5f;
        float ry = (gy + 1.0f) * (0.5f * PH) - 0.5f;

        float x0f = floorf(rx);
        float y0f = floorf(ry);
        int   x0  = (int)x0f;
        int   y0  = (int)y0f;
        float fx  = rx - x0f;
        float fy  = ry - y0f;

        // gx,gy in [-1,1) => x0 in [-1,63], x1 in [0,64]; one-sided masks suffice
        float mx0 = (x0 >= 0)      ? 1.0f : 0.0f;
        float mx1 = (x0 <  PW - 1) ? 1.0f : 0.0f;
        float my0 = (y0 >= 0)      ? 1.0f : 0.0f;
        float my1 = (y0 <  PH - 1) ? 1.0f : 0.0f;

        int cx0 = max(x0, 0);
        int cx1 = min(x0 + 1, PW - 1);
        int cy0 = max(y0, 0);
        int cy1 = min(y0 + 1, PH - 1);

        const float4* base = imgB + (size_t)j * PHW * (PC / 4);
        // Issue all four gathers before consuming (MLP against L2 latency).
        float4 va = base[(cy0 * PW + cx0) * (PC / 4)];
        float4 vb = base[(cy1 * PW + cx0) * (PC / 4)];
        float4 vc = base[(cy0 * PW + cx1) * (PC / 4)];
        float4 vd = base[(cy1 * PW + cx1) * (PC / 4)];

        float wa = (1.0f - fx) * (1.0f - fy) * (mx0 * my0);  // (x0,y0)
        float wb = (1.0f - fx) * fy          * (mx0 * my1);  // (x0,y1)
        float wc = fx * (1.0f - fy)          * (mx1 * my0);  // (x1,y0)
        float wd = fx * fy                   * (mx1 * my1);  // (x1,y1)

        acc.x += wa * va.x + wb * vb.x + wc * vc.x + wd * vd.x;
        acc.y += wa * va.y + wb * vb.y + wc * vc.y + wd * vd.y;
        acc.z += wa * va.z + wb * vb.z + wc * vc.z + wd * vd.z;
        acc.w += wa * va.w + wb * vb.w + wc * vc.w + wd * vd.w;
    }

    // out[b][i][c][h][w], c = cg*4 .. cg*4+3
    float* op = out + ((size_t)(b * PL + i) * PC + cg * 4) * PHW + pix;
    op[0 * PHW] = acc.x;
    op[1 * PHW] = acc.y;
    op[2 * PHW] = acc.z;
    op[3 * PHW] = acc.w;
}

// ---------------------------------------------------------------------------
extern "C" void kernel_launch(void* const* d_in, const int* in_sizes, int n_in,
                              void* d_out, int out_size)
{
    // Bind inputs by element count (robust to metadata ordering):
    // flows = 262144 elems, images = 2097152 elems.
    const float* flows  = (const float*)d_in[0];
    const float* images = (const float*)d_in[1];
    if (n_in >= 2 && in_sizes[0] == IMAGES_ELEMS && in_sizes[1] == FLOWS_ELEMS) {
        flows  = (const float*)d_in[1];
        images = (const float*)d_in[0];
    }
    float* out = (float*)d_out;                    // (2,16,16,64,64)

    // 1) fused prep: cumsum (32 blocks) + channel-last transpose (512 blocks)
    prep_kernel<<<CUM_BLOCKS + TRANS_BLOCKS, 256>>>(flows, images);

    // 2) main pairwise scan
    dim3 grid(PHW / 64, PL, PB);
    pscan_kernel<<<grid, 256>>>(out);
}